// round 14
// baseline (speedup 1.0000x reference)
#include <cuda_runtime.h>
#include <cuda_fp16.h>
#include <stdint.h>

#define Sn 2048
#define Dn 64
#define Hn 16
#define BHn 64

static const size_t OSZ = (size_t)BHn * Sn * Dn;
#define EXP_SCALE 0.1803368801111204f   // 0.125 * log2(e)

__device__ __half gQf[(size_t)BHn * Sn * Dn];
__device__ __half gKf[(size_t)BHn * Sn * Dn];
__device__ __half gVf[(size_t)BHn * Sn * Dn];

// ------------------------------------------------------------------ helpers
__device__ __forceinline__ uint32_t smem_u32(const void* p) {
    uint32_t a;
    asm("{ .reg .u64 t; cvta.to.shared.u64 t, %1; cvt.u32.u64 %0, t; }"
        : "=r"(a) : "l"(p));
    return a;
}

#define SW128(o) ((uint32_t)(o) ^ ((((uint32_t)(o)) >> 3) & 0x70))

__device__ __forceinline__ float ex2f(float x) {
    float y; asm("ex2.approx.ftz.f32 %0, %1;" : "=f"(y) : "f"(x)); return y;
}

__device__ __forceinline__ void cpa16(uint32_t dst, const void* src) {
    asm volatile("cp.async.cg.shared.global [%0], [%1], 16;"
                 :: "r"(dst), "l"(src));
}
#define CPA_COMMIT() asm volatile("cp.async.commit_group;" ::: "memory")
#define CPA_WAIT(n)  asm volatile("cp.async.wait_group %0;" :: "n"(n) : "memory")

__device__ __forceinline__ void ldsm_x4(uint32_t r[4], uint32_t addr) {
    asm volatile("ldmatrix.sync.aligned.m8n8.x4.shared.b16 {%0,%1,%2,%3}, [%4];"
                 : "=r"(r[0]), "=r"(r[1]), "=r"(r[2]), "=r"(r[3]) : "r"(addr));
}
__device__ __forceinline__ void ldsm_x4t(uint32_t r[4], uint32_t addr) {
    asm volatile("ldmatrix.sync.aligned.m8n8.x4.trans.shared.b16 {%0,%1,%2,%3}, [%4];"
                 : "=r"(r[0]), "=r"(r[1]), "=r"(r[2]), "=r"(r[3]) : "r"(addr));
}

__device__ __forceinline__ void mma16816h(float c[4], const uint32_t a[4],
                                          uint32_t b0, uint32_t b1) {
    asm volatile(
        "mma.sync.aligned.m16n8k16.row.col.f32.f16.f16.f32 "
        "{%0,%1,%2,%3}, {%4,%5,%6,%7}, {%8,%9}, {%0,%1,%2,%3};"
        : "+f"(c[0]), "+f"(c[1]), "+f"(c[2]), "+f"(c[3])
        : "r"(a[0]), "r"(a[1]), "r"(a[2]), "r"(a[3]), "r"(b0), "r"(b1));
}

__device__ __forceinline__ uint32_t pack_h2(float a, float b) {
    __half2 h = __floats2half2_rn(a, b);
    return *(uint32_t*)&h;
}

__device__ __forceinline__ void stg_cs_f2(float* p, float a, float b) {
    asm volatile("st.global.cs.v2.f32 [%0], {%1, %2};"
                 :: "l"(p), "f"(a), "f"(b) : "memory");
}

// ---------------------------------------------------------------------------
// Kernel 0: Q,K,V -> fp16.
// ---------------------------------------------------------------------------
__global__ void __launch_bounds__(256)
prep_kernel(const float* __restrict__ Q, const float* __restrict__ K,
            const float* __restrict__ V) {
    const size_t i4 = (size_t)blockIdx.x * 256 + threadIdx.x;
    const int y = blockIdx.y;
    const float* src = (y == 0) ? Q : (y == 1) ? K : V;
    __half* dst = (y == 0) ? gQf : (y == 1) ? gKf : gVf;
    float4 v = ((const float4*)src)[i4];
    uint2 o;
    o.x = pack_h2(v.x, v.y);
    o.y = pack_h2(v.z, v.w);
    ((uint2*)dst)[i4] = o;
}

// ---------------------------------------------------------------------------
// Fused kernel: 128 threads (4 warps), 128 q-rows per CTA, 4 CTAs/SM.
// Both sweeps: warp owns 32 q-rows x full k (same Q fragments, cached once).
//  Sweep A: 64-col K chunks, accumulate row sums in registers (no smem reduce).
//  Sweep B: 64-col K+V chunks; per-16-col group: S -> w -> W store -> AV (regs).
// smem: QF 16K | K stages 2x8K | V stages 2x8K | msk 2K   = 50 KB
// ---------------------------------------------------------------------------
#define F_QF 0
#define F_KB(s) (16384 + (s) * 8192)
#define F_VB(s) (32768 + (s) * 8192)
#define F_MSK 49152
#define F_TOTAL 51200

__global__ void __launch_bounds__(128, 4)
fused_kernel(const int* __restrict__ mask, float* __restrict__ W,
             float* __restrict__ O) {
    extern __shared__ char smem[];
    const uint32_t sb = smem_u32(smem);
    const int tid = threadIdx.x, lid = tid & 31, wid = tid >> 5;
    const int q0 = blockIdx.x * 128, bh = blockIdx.y;
    const int b = bh >> 4;

    char* mskC = smem + F_MSK;
    const size_t bhS = (size_t)bh * Sn;

    // ---------------- prologue: Q tile (128 rows) + sweep-A K chunks 0,1
    #pragma unroll
    for (int j = 0; j < 8; j++) {
        const int f = tid + j * 128;
        const int row = f >> 3, c16 = f & 7;
        const uint32_t sw = SW128(row * 128 + c16 * 16);
        cpa16(sb + F_QF + sw, gQf + (bhS + q0 + row) * Dn + c16 * 8);
    }
    #pragma unroll
    for (int j = 0; j < 4; j++) {
        const int f = tid + j * 128;
        const int row = f >> 3, c16 = f & 7;   // row 0..63
        const uint32_t sw = SW128(row * 128 + c16 * 16);
        cpa16(sb + F_KB(0) + sw, gKf + (bhS + row) * Dn + c16 * 8);
    }
    CPA_COMMIT();
    #pragma unroll
    for (int j = 0; j < 4; j++) {
        const int f = tid + j * 128;
        const int row = f >> 3, c16 = f & 7;
        const uint32_t sw = SW128(row * 128 + c16 * 16);
        cpa16(sb + F_KB(1) + sw, gKf + (bhS + 64 + row) * Dn + c16 * 8);
    }
    CPA_COMMIT();

    #pragma unroll
    for (int j = 0; j < 16; j++) {
        const int i = tid + j * 128;
        mskC[i] = (char)mask[b * Sn + i];
    }

    CPA_WAIT(1);
    __syncthreads();   // Q + K chunk0 ready

    // Q fragments: warp owns rows wid*32 .. +32 (mt = 2 tiles of 16), cached
    uint32_t qf[2][4][4];
    #pragma unroll
    for (int mt = 0; mt < 2; mt++)
        #pragma unroll
        for (int ks = 0; ks < 4; ks++) {
            const uint32_t off = (uint32_t)(wid * 32 + mt * 16 + (lid & 15)) * 128
                               + ks * 32 + (lid >> 4) * 16;
            ldsm_x4(qf[mt][ks], sb + F_QF + SW128(off));
        }

    // ---------------- sweep A: row sums in registers
    float rsum[2][2] = {{0.f, 0.f}, {0.f, 0.f}};

    for (int it = 0; it < 32; it++) {
        const int s = it & 1;
        const int kc = it * 64;
        if (it > 0) {
            if (it == 31) { CPA_WAIT(0); } else { CPA_WAIT(1); }
            __syncthreads();
        }

        #pragma unroll
        for (int g = 0; g < 4; g++) {
            float accS[2][2][4];
            #pragma unroll
            for (int mt = 0; mt < 2; mt++)
                #pragma unroll
                for (int p = 0; p < 2; p++)
                    #pragma unroll
                    for (int j = 0; j < 4; j++) accS[mt][p][j] = 0.0f;

            #pragma unroll
            for (int ks = 0; ks < 4; ks++) {
                const uint32_t boff = (uint32_t)(g * 16 + (lid & 15)) * 128
                                    + ks * 32 + (lid >> 4) * 16;
                uint32_t bF[4];
                ldsm_x4(bF, sb + F_KB(s) + SW128(boff));
                #pragma unroll
                for (int mt = 0; mt < 2; mt++) {
                    mma16816h(accS[mt][0], qf[mt][ks], bF[0], bF[2]);
                    mma16816h(accS[mt][1], qf[mt][ks], bF[1], bF[3]);
                }
            }
            #pragma unroll
            for (int mt = 0; mt < 2; mt++)
                #pragma unroll
                for (int p = 0; p < 2; p++) {
                    const float* c = accS[mt][p];
                    const int kg = kc + g * 16 + p * 8 + (lid & 3) * 2;
                    const int m0 = mskC[kg], m1 = mskC[kg + 1];
                    float e0 = m0 ? 0.f : ex2f(c[0] * EXP_SCALE);
                    float e1 = m1 ? 0.f : ex2f(c[1] * EXP_SCALE);
                    float e2 = m0 ? 0.f : ex2f(c[2] * EXP_SCALE);
                    float e3 = m1 ? 0.f : ex2f(c[3] * EXP_SCALE);
                    rsum[mt][0] += e0 + e1;
                    rsum[mt][1] += e2 + e3;
                }
        }
        __syncthreads();   // K stage s reads complete

        if (it + 2 < 32) {
            const int kn = (it + 2) * 64;
            #pragma unroll
            for (int j = 0; j < 4; j++) {
                const int f = tid + j * 128;
                const int row = f >> 3, c16 = f & 7;
                const uint32_t sw = SW128(row * 128 + c16 * 16);
                cpa16(sb + F_KB(s) + sw, gKf + (bhS + kn + row) * Dn + c16 * 8);
            }
            CPA_COMMIT();
        }
    }

    // quad-reduce row sums (lanes in a quad hold different cols of same rows)
    #pragma unroll
    for (int off = 1; off < 4; off <<= 1) {
        #pragma unroll
        for (int mt = 0; mt < 2; mt++) {
            rsum[mt][0] += __shfl_xor_sync(0xffffffffu, rsum[mt][0], off);
            rsum[mt][1] += __shfl_xor_sync(0xffffffffu, rsum[mt][1], off);
        }
    }
    float ilA[2], ilB[2];
    #pragma unroll
    for (int mt = 0; mt < 2; mt++) {
        ilA[mt] = 1.0f / rsum[mt][0];
        ilB[mt] = 1.0f / rsum[mt][1];
    }

    // ---------------- prologue B: K,V chunks 0,1 (64 rows each)
    #pragma unroll
    for (int j = 0; j < 4; j++) {
        const int f = tid + j * 128;
        const int row = f >> 3, c16 = f & 7;
        const uint32_t sw = SW128(row * 128 + c16 * 16);
        const size_t src = (bhS + row) * Dn + c16 * 8;
        cpa16(sb + F_KB(0) + sw, gKf + src);
        cpa16(sb + F_VB(0) + sw, gVf + src);
    }
    CPA_COMMIT();
    #pragma unroll
    for (int j = 0; j < 4; j++) {
        const int f = tid + j * 128;
        const int row = f >> 3, c16 = f & 7;
        const uint32_t sw = SW128(row * 128 + c16 * 16);
        const size_t src = (bhS + 64 + row) * Dn + c16 * 8;
        cpa16(sb + F_KB(1) + sw, gKf + src);
        cpa16(sb + F_VB(1) + sw, gVf + src);
    }
    CPA_COMMIT();

    const int rA0 = wid * 32 + (lid >> 2);
    float* Wb = W + (size_t)bh * Sn * Sn;
    float* WrA[2]; float* WrB[2];
    #pragma unroll
    for (int mt = 0; mt < 2; mt++) {
        WrA[mt] = Wb + (size_t)(q0 + rA0 + mt * 16) * Sn;
        WrB[mt] = WrA[mt] + 8 * Sn;
    }

    float accO[2][8][4];
    #pragma unroll
    for (int mt = 0; mt < 2; mt++)
        #pragma unroll
        for (int i = 0; i < 8; i++)
            #pragma unroll
            for (int j = 0; j < 4; j++) accO[mt][i][j] = 0.0f;

    CPA_WAIT(1);
    __syncthreads();   // B chunk0 ready

    // ---------------- sweep B: per-16-col pipelined S -> w -> AV
    for (int it = 0; it < 32; it++) {
        const int s = it & 1;
        const int kc = it * 64;
        if (it > 0) {
            if (it == 31) { CPA_WAIT(0); } else { CPA_WAIT(1); }
            __syncthreads();
        }

        #pragma unroll
        for (int g = 0; g < 4; g++) {
            // ---- S for this 16-col group (32 rows x 16 cols per warp)
            float accS[2][2][4];
            #pragma unroll
            for (int mt = 0; mt < 2; mt++)
                #pragma unroll
                for (int p = 0; p < 2; p++)
                    #pragma unroll
                    for (int j = 0; j < 4; j++) accS[mt][p][j] = 0.0f;

            #pragma unroll
            for (int ks = 0; ks < 4; ks++) {
                const uint32_t boff = (uint32_t)(g * 16 + (lid & 15)) * 128
                                    + ks * 32 + (lid >> 4) * 16;
                uint32_t bF[4];
                ldsm_x4(bF, sb + F_KB(s) + SW128(boff));
                #pragma unroll
                for (int mt = 0; mt < 2; mt++) {
                    mma16816h(accS[mt][0], qf[mt][ks], bF[0], bF[2]);
                    mma16816h(accS[mt][1], qf[mt][ks], bF[1], bF[3]);
                }
            }

            // ---- epilogue: w = e*invl, stream W, pack A-fragments (regs)
            uint32_t av_a[2][4];
            #pragma unroll
            for (int mt = 0; mt < 2; mt++) {
                #pragma unroll
                for (int p = 0; p < 2; p++) {
                    const float* c = accS[mt][p];
                    const int col = g * 16 + p * 8 + (lid & 3) * 2;
                    const int kg = kc + col;
                    const int m0 = mskC[kg], m1 = mskC[kg + 1];
                    const float e0 = m0 ? 0.f : ex2f(c[0] * EXP_SCALE);
                    const float e1 = m1 ? 0.f : ex2f(c[1] * EXP_SCALE);
                    const float e2 = m0 ? 0.f : ex2f(c[2] * EXP_SCALE);
                    const float e3 = m1 ? 0.f : ex2f(c[3] * EXP_SCALE);
                    const float w0 = e0 * ilA[mt], w1 = e1 * ilA[mt];
                    const float w2 = e2 * ilB[mt], w3 = e3 * ilB[mt];
                    stg_cs_f2(WrA[mt] + kg, w0, w1);
                    stg_cs_f2(WrB[mt] + kg, w2, w3);
                    av_a[mt][2 * p]     = pack_h2(w0, w1);
                    av_a[mt][2 * p + 1] = pack_h2(w2, w3);
                }
            }

            // ---- AV: O += w @ V for this 16-k group (32 x 64 per warp)
            #pragma unroll
            for (int dg = 0; dg < 4; dg++) {
                const uint32_t voff =
                    (uint32_t)(g * 16 + (lid & 7) + ((lid >> 3) & 1) * 8) * 128
                    + (dg * 16 + (lid >> 4) * 8) * 2;
                uint32_t bF[4];
                ldsm_x4t(bF, sb + F_VB(s) + SW128(voff));
                #pragma unroll
                for (int mt = 0; mt < 2; mt++) {
                    mma16816h(accO[mt][2 * dg],     av_a[mt], bF[0], bF[1]);
                    mma16816h(accO[mt][2 * dg + 1], av_a[mt], bF[2], bF[3]);
                }
            }
        }
        __syncthreads();   // stage s reads complete

        if (it + 2 < 32) {
            const int kn = (it + 2) * 64;
            #pragma unroll
            for (int j = 0; j < 4; j++) {
                const int f = tid + j * 128;
                const int row = f >> 3, c16 = f & 7;
                const uint32_t sw = SW128(row * 128 + c16 * 16);
                const size_t src = (bhS + kn + row) * Dn + c16 * 8;
                cpa16(sb + F_KB(s) + sw, gKf + src);
                cpa16(sb + F_VB(s) + sw, gVf + src);
            }
            CPA_COMMIT();
        }
    }

    float* Ob = O + (bhS + q0) * Dn;
    #pragma unroll
    for (int mt = 0; mt < 2; mt++) {
        const int row = rA0 + mt * 16;
        #pragma unroll
        for (int t = 0; t < 8; t++) {
            const float* c = accO[mt][t];
            const int col = t * 8 + (lid & 3) * 2;
            stg_cs_f2(Ob + (size_t)row * Dn + col, c[0], c[1]);
            stg_cs_f2(Ob + (size_t)(row + 8) * Dn + col, c[2], c[3]);
        }
    }
}

// ---------------------------------------------------------------------------
extern "C" void kernel_launch(void* const* d_in, const int* in_sizes, int n_in,
                              void* d_out, int out_size) {
    const float* Q    = (const float*)d_in[0];
    const float* K    = (const float*)d_in[1];
    const float* V    = (const float*)d_in[2];
    const int*   mask = (const int*)  d_in[3];

    float* O = (float*)d_out;
    float* W = O + OSZ;

    cudaFuncSetAttribute(fused_kernel, cudaFuncAttributeMaxDynamicSharedMemorySize, F_TOTAL);

    {
        dim3 grid((unsigned)(OSZ / 4 / 256), 3);
        prep_kernel<<<grid, 256>>>(Q, K, V);
    }
    {
        dim3 grid(Sn / 128, BHn);
        fused_kernel<<<grid, 128, F_TOTAL>>>(mask, W, O);
    }
    (void)in_sizes; (void)n_in; (void)out_size;
}

// round 16
// speedup vs baseline: 1.3231x; 1.3231x over previous
#include <cuda_runtime.h>
#include <cuda_fp16.h>
#include <stdint.h>

#define Sn 2048
#define Dn 64
#define Hn 16
#define Bn 4
#define BHn 64

static const size_t OSZ = (size_t)BHn * Sn * Dn;
#define EXP_SCALE 0.1803368801111204f   // 0.125 * log2(e)

__device__ __half gQf[(size_t)BHn * Sn * Dn];
__device__ __half gKf[(size_t)BHn * Sn * Dn];
__device__ __half gVf[(size_t)BHn * Sn * Dn];
__device__ __half gKc[(size_t)BHn * Sn * Dn];   // compacted K (unmasked cols)
__device__ int gIdx[Bn][Sn];
__device__ int gCnt[Bn];

// ------------------------------------------------------------------ helpers
__device__ __forceinline__ uint32_t smem_u32(const void* p) {
    uint32_t a;
    asm("{ .reg .u64 t; cvta.to.shared.u64 t, %1; cvt.u32.u64 %0, t; }"
        : "=r"(a) : "l"(p));
    return a;
}

#define SW128(o) ((uint32_t)(o) ^ ((((uint32_t)(o)) >> 3) & 0x70))

__device__ __forceinline__ float ex2f(float x) {
    float y; asm("ex2.approx.ftz.f32 %0, %1;" : "=f"(y) : "f"(x)); return y;
}

__device__ __forceinline__ void cpa16(uint32_t dst, const void* src) {
    asm volatile("cp.async.cg.shared.global [%0], [%1], 16;"
                 :: "r"(dst), "l"(src));
}
#define CPA_COMMIT() asm volatile("cp.async.commit_group;" ::: "memory")
#define CPA_WAIT(n)  asm volatile("cp.async.wait_group %0;" :: "n"(n) : "memory")

__device__ __forceinline__ void ldsm_x4(uint32_t r[4], uint32_t addr) {
    asm volatile("ldmatrix.sync.aligned.m8n8.x4.shared.b16 {%0,%1,%2,%3}, [%4];"
                 : "=r"(r[0]), "=r"(r[1]), "=r"(r[2]), "=r"(r[3]) : "r"(addr));
}
__device__ __forceinline__ void ldsm_x4t(uint32_t r[4], uint32_t addr) {
    asm volatile("ldmatrix.sync.aligned.m8n8.x4.trans.shared.b16 {%0,%1,%2,%3}, [%4];"
                 : "=r"(r[0]), "=r"(r[1]), "=r"(r[2]), "=r"(r[3]) : "r"(addr));
}

__device__ __forceinline__ void mma16816h(float c[4], const uint32_t a[4],
                                          uint32_t b0, uint32_t b1) {
    asm volatile(
        "mma.sync.aligned.m16n8k16.row.col.f32.f16.f16.f32 "
        "{%0,%1,%2,%3}, {%4,%5,%6,%7}, {%8,%9}, {%0,%1,%2,%3};"
        : "+f"(c[0]), "+f"(c[1]), "+f"(c[2]), "+f"(c[3])
        : "r"(a[0]), "r"(a[1]), "r"(a[2]), "r"(a[3]), "r"(b0), "r"(b1));
}

__device__ __forceinline__ uint32_t pack_h2(float a, float b) {
    __half2 h = __floats2half2_rn(a, b);
    return *(uint32_t*)&h;
}

__device__ __forceinline__ void stg_cs_f2(float* p, float a, float b) {
    asm volatile("st.global.cs.v2.f32 [%0], {%1, %2};"
                 :: "l"(p), "f"(a), "f"(b) : "memory");
}

// ---------------------------------------------------------------------------
// Kernel 0: Q,K,V -> fp16.
// ---------------------------------------------------------------------------
__global__ void __launch_bounds__(256)
prep_kernel(const float* __restrict__ Q, const float* __restrict__ K,
            const float* __restrict__ V) {
    const size_t i4 = (size_t)blockIdx.x * 256 + threadIdx.x;
    const int y = blockIdx.y;
    const float* src = (y == 0) ? Q : (y == 1) ? K : V;
    __half* dst = (y == 0) ? gQf : (y == 1) ? gKf : gVf;
    float4 v = ((const float4*)src)[i4];
    uint2 o;
    o.x = pack_h2(v.x, v.y);
    o.y = pack_h2(v.z, v.w);
    ((uint2*)dst)[i4] = o;
}

// ---------------------------------------------------------------------------
// Kernel 0b: per-batch compaction index (64 threads, 1 block per batch).
// ---------------------------------------------------------------------------
__global__ void __launch_bounds__(64)
compact_idx_kernel(const int* __restrict__ mask) {
    const int b = blockIdx.x, t = threadIdx.x;
    const int base = t * 32;
    int loc[32];
    int cnt = 0;
    #pragma unroll
    for (int i = 0; i < 32; i++) {
        if (mask[b * Sn + base + i] == 0) loc[cnt++] = base + i;
    }
    __shared__ int s[64];
    s[t] = cnt;
    __syncthreads();
    int off = 0;
    for (int j = 0; j < t; j++) off += s[j];
    for (int i = 0; i < cnt; i++) gIdx[b][off + i] = loc[i];
    if (t == 63) gCnt[b] = off + cnt;
}

// ---------------------------------------------------------------------------
// Kernel 0c: gather compacted K rows (zero-pad beyond L).
// grid (Sn/16, BHn), block 128: 16 rows x 8 x 16B per block.  (uint4 = 16B!)
// ---------------------------------------------------------------------------
__global__ void __launch_bounds__(128)
gather_k_kernel() {
    const int bh = blockIdx.y, b = bh >> 4;
    const int j = blockIdx.x * 16 + (threadIdx.x >> 3);
    const int c = threadIdx.x & 7;
    const int L = gCnt[b];
    uint4 v = make_uint4(0u, 0u, 0u, 0u);
    if (j < L) {
        const int src = gIdx[b][j];
        v = *(const uint4*)(gKf + ((size_t)bh * Sn + src) * Dn + c * 8);
    }
    *(uint4*)(gKc + ((size_t)bh * Sn + j) * Dn + c * 8) = v;
}

// ---------------------------------------------------------------------------
// Fused kernel: 128 threads (4 warps), 128 q-rows per CTA, 3 CTAs/SM.
//  Sweep A: COMPACTED K chunks (~L/64 iters), row sums in registers.
//  Sweep B: 64-col K+V chunks; per-16-col group: S -> w -> W store -> AV.
// smem: QF 16K | K stages 2x8K | V stages 2x8K | msk 2K = 50 KB
// ---------------------------------------------------------------------------
#define F_QF 0
#define F_KB(s) (16384 + (s) * 8192)
#define F_VB(s) (32768 + (s) * 8192)
#define F_MSK 49152
#define F_TOTAL 51200

__global__ void __launch_bounds__(128, 3)
fused_kernel(const int* __restrict__ mask, float* __restrict__ W,
             float* __restrict__ O) {
    extern __shared__ char smem[];
    const uint32_t sb = smem_u32(smem);
    const int tid = threadIdx.x, lid = tid & 31, wid = tid >> 5;
    const int q0 = blockIdx.x * 128, bh = blockIdx.y;
    const int b = bh >> 4;

    char* mskC = smem + F_MSK;
    const size_t bhS = (size_t)bh * Sn;

    const int L = gCnt[b];
    const int nIt = (L + 63) >> 6;

    // ---------------- prologue: Q tile + compacted-K chunks 0,1
    #pragma unroll
    for (int j = 0; j < 8; j++) {
        const int f = tid + j * 128;
        const int row = f >> 3, c16 = f & 7;
        const uint32_t sw = SW128(row * 128 + c16 * 16);
        cpa16(sb + F_QF + sw, gQf + (bhS + q0 + row) * Dn + c16 * 8);
    }
    #pragma unroll
    for (int j = 0; j < 4; j++) {
        const int f = tid + j * 128;
        const int row = f >> 3, c16 = f & 7;   // row 0..63
        const uint32_t sw = SW128(row * 128 + c16 * 16);
        cpa16(sb + F_KB(0) + sw, gKc + (bhS + row) * Dn + c16 * 8);
    }
    CPA_COMMIT();
    #pragma unroll
    for (int j = 0; j < 4; j++) {
        const int f = tid + j * 128;
        const int row = f >> 3, c16 = f & 7;
        const uint32_t sw = SW128(row * 128 + c16 * 16);
        cpa16(sb + F_KB(1) + sw, gKc + (bhS + 64 + row) * Dn + c16 * 8);
    }
    CPA_COMMIT();

    #pragma unroll
    for (int j = 0; j < 16; j++) {
        const int i = tid + j * 128;
        mskC[i] = (char)mask[b * Sn + i];
    }

    CPA_WAIT(1);
    __syncthreads();   // Q + chunk0 ready

    // Q fragments: warp owns rows wid*32 .. +32 (mt = 2 tiles of 16), cached
    uint32_t qf[2][4][4];
    #pragma unroll
    for (int mt = 0; mt < 2; mt++)
        #pragma unroll
        for (int ks = 0; ks < 4; ks++) {
            const uint32_t off = (uint32_t)(wid * 32 + mt * 16 + (lid & 15)) * 128
                               + ks * 32 + (lid >> 4) * 16;
            ldsm_x4(qf[mt][ks], sb + F_QF + SW128(off));
        }

    // ---------------- sweep A: row sums over compacted columns
    float rsum[2][2] = {{0.f, 0.f}, {0.f, 0.f}};

    for (int it = 0; it < nIt; it++) {
        const int s = it & 1;
        const int kc = it * 64;
        if (it > 0) {
            if (it == nIt - 1) { CPA_WAIT(0); } else { CPA_WAIT(1); }
            __syncthreads();
        }

        #pragma unroll
        for (int g = 0; g < 4; g++) {
            float accS[2][2][4];
            #pragma unroll
            for (int mt = 0; mt < 2; mt++)
                #pragma unroll
                for (int p = 0; p < 2; p++)
                    #pragma unroll
                    for (int j = 0; j < 4; j++) accS[mt][p][j] = 0.0f;

            #pragma unroll
            for (int ks = 0; ks < 4; ks++) {
                const uint32_t boff = (uint32_t)(g * 16 + (lid & 15)) * 128
                                    + ks * 32 + (lid >> 4) * 16;
                uint32_t bF[4];
                ldsm_x4(bF, sb + F_KB(s) + SW128(boff));
                #pragma unroll
                for (int mt = 0; mt < 2; mt++) {
                    mma16816h(accS[mt][0], qf[mt][ks], bF[0], bF[2]);
                    mma16816h(accS[mt][1], qf[mt][ks], bF[1], bF[3]);
                }
            }
            #pragma unroll
            for (int mt = 0; mt < 2; mt++)
                #pragma unroll
                for (int p = 0; p < 2; p++) {
                    const float* c = accS[mt][p];
                    const int kg = kc + g * 16 + p * 8 + (lid & 3) * 2;
                    // compacted: all columns unmasked; only the global tail
                    // (kg >= L) is padding and must not contribute.
                    if (kg + 1 < L) {
                        rsum[mt][0] += ex2f(c[0] * EXP_SCALE) + ex2f(c[1] * EXP_SCALE);
                        rsum[mt][1] += ex2f(c[2] * EXP_SCALE) + ex2f(c[3] * EXP_SCALE);
                    } else {
                        float e0 = (kg < L) ? ex2f(c[0] * EXP_SCALE) : 0.f;
                        float e1 = (kg + 1 < L) ? ex2f(c[1] * EXP_SCALE) : 0.f;
                        float e2 = (kg < L) ? ex2f(c[2] * EXP_SCALE) : 0.f;
                        float e3 = (kg + 1 < L) ? ex2f(c[3] * EXP_SCALE) : 0.f;
                        rsum[mt][0] += e0 + e1;
                        rsum[mt][1] += e2 + e3;
                    }
                }
        }
        __syncthreads();   // K stage s reads complete

        if (it + 2 < nIt) {
            const int kn = (it + 2) * 64;
            #pragma unroll
            for (int j = 0; j < 4; j++) {
                const int f = tid + j * 128;
                const int row = f >> 3, c16 = f & 7;
                const uint32_t sw = SW128(row * 128 + c16 * 16);
                cpa16(sb + F_KB(s) + sw, gKc + (bhS + kn + row) * Dn + c16 * 8);
            }
            CPA_COMMIT();
        }
    }

    // quad-reduce row sums (lanes in a quad hold different cols of same rows)
    #pragma unroll
    for (int off = 1; off < 4; off <<= 1) {
        #pragma unroll
        for (int mt = 0; mt < 2; mt++) {
            rsum[mt][0] += __shfl_xor_sync(0xffffffffu, rsum[mt][0], off);
            rsum[mt][1] += __shfl_xor_sync(0xffffffffu, rsum[mt][1], off);
        }
    }
    float ilA[2], ilB[2];
    #pragma unroll
    for (int mt = 0; mt < 2; mt++) {
        ilA[mt] = 1.0f / rsum[mt][0];
        ilB[mt] = 1.0f / rsum[mt][1];
    }

    // ---------------- prologue B: K,V chunks 0,1 (64 rows each, FULL K)
    #pragma unroll
    for (int j = 0; j < 4; j++) {
        const int f = tid + j * 128;
        const int row = f >> 3, c16 = f & 7;
        const uint32_t sw = SW128(row * 128 + c16 * 16);
        const size_t src = (bhS + row) * Dn + c16 * 8;
        cpa16(sb + F_KB(0) + sw, gKf + src);
        cpa16(sb + F_VB(0) + sw, gVf + src);
    }
    CPA_COMMIT();
    #pragma unroll
    for (int j = 0; j < 4; j++) {
        const int f = tid + j * 128;
        const int row = f >> 3, c16 = f & 7;
        const uint32_t sw = SW128(row * 128 + c16 * 16);
        const size_t src = (bhS + 64 + row) * Dn + c16 * 8;
        cpa16(sb + F_KB(1) + sw, gKf + src);
        cpa16(sb + F_VB(1) + sw, gVf + src);
    }
    CPA_COMMIT();

    const int rA0 = wid * 32 + (lid >> 2);
    float* Wb = W + (size_t)bh * Sn * Sn;
    float* WrA[2]; float* WrB[2];
    #pragma unroll
    for (int mt = 0; mt < 2; mt++) {
        WrA[mt] = Wb + (size_t)(q0 + rA0 + mt * 16) * Sn;
        WrB[mt] = WrA[mt] + 8 * Sn;
    }

    float accO[2][8][4];
    #pragma unroll
    for (int mt = 0; mt < 2; mt++)
        #pragma unroll
        for (int i = 0; i < 8; i++)
            #pragma unroll
            for (int j = 0; j < 4; j++) accO[mt][i][j] = 0.0f;

    CPA_WAIT(1);
    __syncthreads();   // B chunk0 ready

    // ---------------- sweep B: per-16-col pipelined S -> w -> AV
    for (int it = 0; it < 32; it++) {
        const int s = it & 1;
        const int kc = it * 64;
        if (it > 0) {
            if (it == 31) { CPA_WAIT(0); } else { CPA_WAIT(1); }
            __syncthreads();
        }

        #pragma unroll
        for (int g = 0; g < 4; g++) {
            // ---- S for this 16-col group (32 rows x 16 cols per warp)
            float accS[2][2][4];
            #pragma unroll
            for (int mt = 0; mt < 2; mt++)
                #pragma unroll
                for (int p = 0; p < 2; p++)
                    #pragma unroll
                    for (int j = 0; j < 4; j++) accS[mt][p][j] = 0.0f;

            #pragma unroll
            for (int ks = 0; ks < 4; ks++) {
                const uint32_t boff = (uint32_t)(g * 16 + (lid & 15)) * 128
                                    + ks * 32 + (lid >> 4) * 16;
                uint32_t bF[4];
                ldsm_x4(bF, sb + F_KB(s) + SW128(boff));
                #pragma unroll
                for (int mt = 0; mt < 2; mt++) {
                    mma16816h(accS[mt][0], qf[mt][ks], bF[0], bF[2]);
                    mma16816h(accS[mt][1], qf[mt][ks], bF[1], bF[3]);
                }
            }

            // ---- epilogue: w = e*invl, stream W, pack A-fragments (regs)
            uint32_t av_a[2][4];
            #pragma unroll
            for (int mt = 0; mt < 2; mt++) {
                #pragma unroll
                for (int p = 0; p < 2; p++) {
                    const float* c = accS[mt][p];
                    const int col = g * 16 + p * 8 + (lid & 3) * 2;
                    const int kg = kc + col;
                    const int m0 = mskC[kg], m1 = mskC[kg + 1];
                    const float e0 = m0 ? 0.f : ex2f(c[0] * EXP_SCALE);
                    const float e1 = m1 ? 0.f : ex2f(c[1] * EXP_SCALE);
                    const float e2 = m0 ? 0.f : ex2f(c[2] * EXP_SCALE);
                    const float e3 = m1 ? 0.f : ex2f(c[3] * EXP_SCALE);
                    const float w0 = e0 * ilA[mt], w1 = e1 * ilA[mt];
                    const float w2 = e2 * ilB[mt], w3 = e3 * ilB[mt];
                    stg_cs_f2(WrA[mt] + kg, w0, w1);
                    stg_cs_f2(WrB[mt] + kg, w2, w3);
                    av_a[mt][2 * p]     = pack_h2(w0, w1);
                    av_a[mt][2 * p + 1] = pack_h2(w2, w3);
                }
            }

            // ---- AV: O += w @ V for this 16-k group (32 x 64 per warp)
            #pragma unroll
            for (int dg = 0; dg < 4; dg++) {
                const uint32_t voff =
                    (uint32_t)(g * 16 + (lid & 7) + ((lid >> 3) & 1) * 8) * 128
                    + (dg * 16 + (lid >> 4) * 8) * 2;
                uint32_t bF[4];
                ldsm_x4t(bF, sb + F_VB(s) + SW128(voff));
                #pragma unroll
                for (int mt = 0; mt < 2; mt++) {
                    mma16816h(accO[mt][2 * dg],     av_a[mt], bF[0], bF[1]);
                    mma16816h(accO[mt][2 * dg + 1], av_a[mt], bF[2], bF[3]);
                }
            }
        }
        __syncthreads();   // stage s reads complete

        if (it + 2 < 32) {
            const int kn = (it + 2) * 64;
            #pragma unroll
            for (int j = 0; j < 4; j++) {
                const int f = tid + j * 128;
                const int row = f >> 3, c16 = f & 7;
                const uint32_t sw = SW128(row * 128 + c16 * 16);
                const size_t src = (bhS + kn + row) * Dn + c16 * 8;
                cpa16(sb + F_KB(s) + sw, gKf + src);
                cpa16(sb + F_VB(s) + sw, gVf + src);
            }
            CPA_COMMIT();
        }
    }

    float* Ob = O + (bhS + q0) * Dn;
    #pragma unroll
    for (int mt = 0; mt < 2; mt++) {
        const int row = rA0 + mt * 16;
        #pragma unroll
        for (int t = 0; t < 8; t++) {
            const float* c = accO[mt][t];
            const int col = t * 8 + (lid & 3) * 2;
            stg_cs_f2(Ob + (size_t)row * Dn + col, c[0], c[1]);
            stg_cs_f2(Ob + (size_t)(row + 8) * Dn + col, c[2], c[3]);
        }
    }
}

// ---------------------------------------------------------------------------
extern "C" void kernel_launch(void* const* d_in, const int* in_sizes, int n_in,
                              void* d_out, int out_size) {
    const float* Q    = (const float*)d_in[0];
    const float* K    = (const float*)d_in[1];
    const float* V    = (const float*)d_in[2];
    const int*   mask = (const int*)  d_in[3];

    float* O = (float*)d_out;
    float* W = O + OSZ;

    cudaFuncSetAttribute(fused_kernel, cudaFuncAttributeMaxDynamicSharedMemorySize, F_TOTAL);

    {
        dim3 grid((unsigned)(OSZ / 4 / 256), 3);
        prep_kernel<<<grid, 256>>>(Q, K, V);
    }
    compact_idx_kernel<<<Bn, 64>>>(mask);
    {
        dim3 grid(Sn / 16, BHn);
        gather_k_kernel<<<grid, 128>>>();
    }
    {
        dim3 grid(Sn / 128, BHn);
        fused_kernel<<<grid, 128, F_TOTAL>>>(mask, W, O);
    }
    (void)in_sizes; (void)n_in; (void)out_size;
}